// round 7
// baseline (speedup 1.0000x reference)
#include <cuda_runtime.h>
#include <cuda_bf16.h>
#include <math.h>

// Problem constants (fixed by the dataset)
#define NN 8192      // nodes
#define EE 24576     // edges
#define DD 4         // node feature dim
#define HH 100       // hidden units

// ---------------------------------------------------------------------------
// Device scratch (no allocations allowed in kernel_launch)
// ---------------------------------------------------------------------------
__device__ int   g_idx_i[EE];
__device__ int   g_idx_o[EE];
__device__ float g_mi[NN * DD];
__device__ float g_mo[NN * DD];
__device__ unsigned int g_bar;          // software grid barrier counter

// ---------------------------------------------------------------------------
// Kernel 1: recover idx_i / idx_o from the dense one-hot incidence matrices,
// and (prologue, subset of blocks) zero the scatter accumulators + barrier.
//
// Each column of Ri/Ro [N, E] (row-major) has exactly one 1.0; compute
//   fidx = sum_r r * M[r, c],  found = sum_r M[r, c]
// over a row-chunk. Exactly one (block-row) chunk finds the 1.0 per column,
// so the writer is unique -> plain store, no atomics.
// This kernel is the HBM roofline: 2 * N * E * 4B = 1.61 GB streamed once.
// Converged at ~7.25 TB/s (R4 config: BATCH 8, 4 blocks/SM; BATCH 16 neutral,
// persistent grid-stride regressed).
// ---------------------------------------------------------------------------
#define SCAN_THREADS     256
#define COLS_PER_BLOCK   (SCAN_THREADS * 4)      // 1024
#define ROW_CHUNKS       64
#define ROWS_PER_CHUNK   (NN / ROW_CHUNKS)       // 128
#define BATCH            8

__global__ __launch_bounds__(SCAN_THREADS, 4)
void find_idx_kernel(const float* __restrict__ Ri, const float* __restrict__ Ro) {
    // --- prologue: zero g_mi / g_mo and the grid-barrier counter (ready
    //     before the fused kernel via kernel-boundary ordering).
    if (blockIdx.z == 0 && blockIdx.y < 8) {
        int t = (blockIdx.y * gridDim.x + blockIdx.x) * SCAN_THREADS + threadIdx.x;
        if (t < NN * DD) { g_mi[t] = 0.0f; g_mo[t] = 0.0f; }
        if (t == 0) g_bar = 0u;
    }

    const float* M   = (blockIdx.z == 0) ? Ri : Ro;
    int*         out = (blockIdx.z == 0) ? g_idx_i : g_idx_o;

    const int col = blockIdx.x * COLS_PER_BLOCK + threadIdx.x * 4;
    const int r0  = blockIdx.y * ROWS_PER_CHUNK;

    const float4* p = reinterpret_cast<const float4*>(M + (long)r0 * EE + col);
    const int row_stride4 = EE / 4;  // float4 elements per row

    float fi0 = 0.f, fi1 = 0.f, fi2 = 0.f, fi3 = 0.f;
    float ff0 = 0.f, ff1 = 0.f, ff2 = 0.f, ff3 = 0.f;

    for (int rb = 0; rb < ROWS_PER_CHUNK; rb += BATCH) {
        // front-batch BATCH independent LDG.128s (deep MLP)
        float4 v[BATCH];
        #pragma unroll
        for (int j = 0; j < BATCH; ++j)
            v[j] = __ldcs(p + (long)(rb + j) * row_stride4);   // streaming

        #pragma unroll
        for (int j = 0; j < BATCH; ++j) {
            float fr = (float)(r0 + rb + j);
            fi0 = fmaf(v[j].x, fr, fi0); ff0 += v[j].x;
            fi1 = fmaf(v[j].y, fr, fi1); ff1 += v[j].y;
            fi2 = fmaf(v[j].z, fr, fi2); ff2 += v[j].z;
            fi3 = fmaf(v[j].w, fr, fi3); ff3 += v[j].w;
        }
    }

    if (ff0 != 0.f) out[col + 0] = (int)fi0;
    if (ff1 != 0.f) out[col + 1] = (int)fi1;
    if (ff2 != 0.f) out[col + 2] = (int)fi2;
    if (ff3 != 0.f) out[col + 3] = (int)fi3;
}

// ---------------------------------------------------------------------------
// Fast device math
// ---------------------------------------------------------------------------
__device__ __forceinline__ float fast_tanh(float x) {
    float y;
    asm("tanh.approx.f32 %0, %1;" : "=f"(y) : "f"(x));
    return y;
}

// ---------------------------------------------------------------------------
// Kernel 2 (fused): edge scatter + grid barrier + MLP.
//
// Phase A: one edge per thread:
//   mi[idx_i[k]] += e[k] * X[idx_o[k]] ; mo[idx_o[k]] += e[k] * X[idx_i[k]]
// (weight preload into smem overlaps phase A)
// Software grid barrier: 256 blocks x 128 threads, <= 8 blocks/SM resource
// footprint -> all blocks co-resident in wave 1, spin is deadlock-free.
// g_bar is zeroed by find_idx_kernel each iteration (kernel-boundary order).
// Phase B: out = sigmoid( tanh([mi,mo,X] @ W1 + b1) @ W2 + b2 )
// 4 threads per node, 25 hidden units each, shfl reduce, tanh.approx.
// ---------------------------------------------------------------------------
#define FUSED_THREADS 128
#define FUSED_BLOCKS  256
#define TPN 4                 // threads per node
#define HPT (HH / TPN)        // 25 hidden units per thread

__global__ __launch_bounds__(FUSED_THREADS)
void scatter_mlp_kernel(const float* __restrict__ X,
                        const float* __restrict__ e,
                        const float* __restrict__ W1, const float* __restrict__ b1,
                        const float* __restrict__ W2, const float* __restrict__ b2,
                        float* __restrict__ out) {
    __shared__ float sW1[3 * DD * HH];   // [12][100] row-major
    __shared__ float sb1[HH];
    __shared__ float sW2[HH];

    // --- weight preload (overlaps the scatter phase; sync comes later) ---
    for (int i = threadIdx.x; i < 3 * DD * HH; i += FUSED_THREADS) sW1[i] = W1[i];
    for (int i = threadIdx.x; i < HH; i += FUSED_THREADS) {
        sb1[i] = b1[i];
        sW2[i] = W2[i];
    }

    // --- Phase A: per-edge scatter (one edge per thread) ---
    int k = blockIdx.x * FUSED_THREADS + threadIdx.x;
    if (k < EE) {
        int   ii = g_idx_i[k];
        int   io = g_idx_o[k];
        float ek = e[k];

        float4 xo = reinterpret_cast<const float4*>(X)[io];
        float4 xi = reinterpret_cast<const float4*>(X)[ii];

        float* mi = g_mi + 4 * ii;
        atomicAdd(mi + 0, ek * xo.x);
        atomicAdd(mi + 1, ek * xo.y);
        atomicAdd(mi + 2, ek * xo.z);
        atomicAdd(mi + 3, ek * xo.w);

        float* mo = g_mo + 4 * io;
        atomicAdd(mo + 0, ek * xi.x);
        atomicAdd(mo + 1, ek * xi.y);
        atomicAdd(mo + 2, ek * xi.z);
        atomicAdd(mo + 3, ek * xi.w);
    }

    // --- software grid barrier ---
    __syncthreads();                 // all block's atomics issued
    __threadfence();                 // make them visible device-wide
    if (threadIdx.x == 0) {
        atomicAdd(&g_bar, 1u);
        while (atomicAdd(&g_bar, 0u) < (unsigned)gridDim.x) { }
    }
    __syncthreads();                 // release whole block; also fences smem weights

    // --- Phase B: fused MLP ---
    int t = blockIdx.x * FUSED_THREADS + threadIdx.x;
    int n = t / TPN;          // node
    int q = t % TPN;          // quarter of hidden units
    if (n >= NN) return;

    float in[3 * DD];
    float4 a = reinterpret_cast<const float4*>(g_mi)[n];
    float4 b = reinterpret_cast<const float4*>(g_mo)[n];
    float4 c = reinterpret_cast<const float4*>(X)[n];
    in[0] = a.x; in[1] = a.y; in[2]  = a.z; in[3]  = a.w;
    in[4] = b.x; in[5] = b.y; in[6]  = b.z; in[7]  = b.w;
    in[8] = c.x; in[9] = c.y; in[10] = c.z; in[11] = c.w;

    float acc = 0.0f;
    const int j0 = q * HPT;
    #pragma unroll 5
    for (int jj = 0; jj < HPT; ++jj) {
        const int j = j0 + jj;
        float s = sb1[j];
        #pragma unroll
        for (int i = 0; i < 3 * DD; ++i)
            s = fmaf(in[i], sW1[i * HH + j], s);
        acc = fmaf(fast_tanh(s), sW2[j], acc);
    }

    // reduce the 4 partial sums within the node's thread quad
    acc += __shfl_xor_sync(0xFFFFFFFFu, acc, 1);
    acc += __shfl_xor_sync(0xFFFFFFFFu, acc, 2);

    if (q == 0) {
        acc += b2[0];
        out[n] = 1.0f / (1.0f + __expf(-acc));
    }
}

// ---------------------------------------------------------------------------
// Launch
// Inputs (metadata order): X, e, Ri, Ro, W1, b1, W2, b2
// ---------------------------------------------------------------------------
extern "C" void kernel_launch(void* const* d_in, const int* in_sizes, int n_in,
                              void* d_out, int out_size) {
    const float* X  = (const float*)d_in[0];
    const float* e  = (const float*)d_in[1];
    const float* Ri = (const float*)d_in[2];
    const float* Ro = (const float*)d_in[3];
    const float* W1 = (const float*)d_in[4];
    const float* b1 = (const float*)d_in[5];
    const float* W2 = (const float*)d_in[6];
    const float* b2 = (const float*)d_in[7];
    float* out = (float*)d_out;

    // 1) recover indices from dense one-hot matrices (HBM-bound) + zero accs
    dim3 grid(EE / COLS_PER_BLOCK, ROW_CHUNKS, 2);   // (24, 64, 2) = 3072 blocks
    find_idx_kernel<<<grid, SCAN_THREADS>>>(Ri, Ro);

    // 2) fused scatter + grid barrier + MLP
    scatter_mlp_kernel<<<FUSED_BLOCKS, FUSED_THREADS>>>(
        X, e, W1, b1, W2, b2, out);
}

// round 8
// speedup vs baseline: 1.0082x; 1.0082x over previous
#include <cuda_runtime.h>
#include <cuda_bf16.h>
#include <math.h>

// Problem constants (fixed by the dataset)
#define NN 8192      // nodes
#define EE 24576     // edges
#define DD 4         // node feature dim
#define HH 100       // hidden units

// ---------------------------------------------------------------------------
// Device scratch (no allocations allowed in kernel_launch)
// ---------------------------------------------------------------------------
__device__ unsigned int g_tag[EE];     // per-edge rendezvous: 0 = empty, else idx+1
__device__ float g_mi[NN * DD];
__device__ float g_mo[NN * DD];

// ---------------------------------------------------------------------------
// Kernel 1: scan the dense one-hot incidence matrices AND scatter inline.
//
// Each column of Ri/Ro [N, E] (row-major) has exactly one 1.0; over a row
// chunk compute fidx = sum_r r*M[r,c], found = sum_r M[r,c]. The unique chunk
// holding the 1.0 knows the index. Per edge there are exactly TWO finders
// (one in a z=0 block -> idx_i, one in a z=1 block -> idx_o). They rendezvous
// via atomicExch on g_tag[k]: first arriver deposits its index (+1); second
// arriver receives the other index in the exchange return value (the value
// travels through the atomic -> no fence needed) and performs the scatter:
//   mi[idx_i] += e[k] * X[idx_o] ;  mo[idx_o] += e[k] * X[idx_i]
//
// This kernel is the HBM roofline: 2 * N * E * 4B = 1.61 GB streamed once.
// Scan config converged at ~7.25 TB/s (BATCH 8, 4 blocks/SM).
//
// Prologue blocks (z=0, y<8, all wave-1) zero mi/mo/tags; earliest epilogue
// scatter is a full chunk-scan (~40us) later -> ordering safe in practice.
// ---------------------------------------------------------------------------
#define SCAN_THREADS     256
#define COLS_PER_BLOCK   (SCAN_THREADS * 4)      // 1024
#define ROW_CHUNKS       64
#define ROWS_PER_CHUNK   (NN / ROW_CHUNKS)       // 128
#define BATCH            8

__device__ __forceinline__ void rendezvous_scatter(
    int c, float fidx, float found, int z,
    const float* __restrict__ X, const float* __restrict__ e)
{
    if (found == 0.f) return;
    int my = (int)fidx;
    unsigned old = atomicExch(&g_tag[c], (unsigned)(my + 1));
    if (old == 0u) return;            // first arriver: just deposited
    int other = (int)old - 1;
    int ii = (z == 0) ? my    : other;
    int io = (z == 0) ? other : my;

    float ek = e[c];
    float4 xo = reinterpret_cast<const float4*>(X)[io];
    float4 xi = reinterpret_cast<const float4*>(X)[ii];

    float* mi = g_mi + 4 * ii;
    atomicAdd(mi + 0, ek * xo.x);
    atomicAdd(mi + 1, ek * xo.y);
    atomicAdd(mi + 2, ek * xo.z);
    atomicAdd(mi + 3, ek * xo.w);

    float* mo = g_mo + 4 * io;
    atomicAdd(mo + 0, ek * xi.x);
    atomicAdd(mo + 1, ek * xi.y);
    atomicAdd(mo + 2, ek * xi.z);
    atomicAdd(mo + 3, ek * xi.w);
}

__global__ __launch_bounds__(SCAN_THREADS, 4)
void find_scatter_kernel(const float* __restrict__ Ri,
                         const float* __restrict__ Ro,
                         const float* __restrict__ X,
                         const float* __restrict__ e) {
    // --- prologue: zero accumulators + rendezvous tags (wave-1 blocks) ---
    if (blockIdx.z == 0 && blockIdx.y < 8) {
        int t = (blockIdx.y * gridDim.x + blockIdx.x) * SCAN_THREADS + threadIdx.x;
        if (t < NN * DD) { g_mi[t] = 0.0f; g_mo[t] = 0.0f; }
        if (t < EE)      g_tag[t] = 0u;
    }

    const int z = blockIdx.z;
    const float* M = (z == 0) ? Ri : Ro;

    const int col = blockIdx.x * COLS_PER_BLOCK + threadIdx.x * 4;
    const int r0  = blockIdx.y * ROWS_PER_CHUNK;

    const float4* p = reinterpret_cast<const float4*>(M + (long)r0 * EE + col);
    const int row_stride4 = EE / 4;  // float4 elements per row

    float fi0 = 0.f, fi1 = 0.f, fi2 = 0.f, fi3 = 0.f;
    float ff0 = 0.f, ff1 = 0.f, ff2 = 0.f, ff3 = 0.f;

    for (int rb = 0; rb < ROWS_PER_CHUNK; rb += BATCH) {
        // front-batch BATCH independent LDG.128s (deep MLP)
        float4 v[BATCH];
        #pragma unroll
        for (int j = 0; j < BATCH; ++j)
            v[j] = __ldcs(p + (long)(rb + j) * row_stride4);   // streaming

        #pragma unroll
        for (int j = 0; j < BATCH; ++j) {
            float fr = (float)(r0 + rb + j);
            fi0 = fmaf(v[j].x, fr, fi0); ff0 += v[j].x;
            fi1 = fmaf(v[j].y, fr, fi1); ff1 += v[j].y;
            fi2 = fmaf(v[j].z, fr, fi2); ff2 += v[j].z;
            fi3 = fmaf(v[j].w, fr, fi3); ff3 += v[j].w;
        }
    }

    // --- epilogue: rendezvous + inline scatter (second arriver does work) ---
    rendezvous_scatter(col + 0, fi0, ff0, z, X, e);
    rendezvous_scatter(col + 1, fi1, ff1, z, X, e);
    rendezvous_scatter(col + 2, fi2, ff2, z, X, e);
    rendezvous_scatter(col + 3, fi3, ff3, z, X, e);
}

// ---------------------------------------------------------------------------
// Fast device math
// ---------------------------------------------------------------------------
__device__ __forceinline__ float fast_tanh(float x) {
    float y;
    asm("tanh.approx.f32 %0, %1;" : "=f"(y) : "f"(x));
    return y;
}

// ---------------------------------------------------------------------------
// Kernel 2: fused MLP  out = sigmoid( tanh([mi,mo,X] @ W1 + b1) @ W2 + b2 )
// 4 threads per node, 25 hidden units each, shfl reduce, tanh.approx (MUFU).
// ---------------------------------------------------------------------------
#define MLP_THREADS 128
#define TPN 4                 // threads per node
#define HPT (HH / TPN)        // 25 hidden units per thread

__global__ __launch_bounds__(MLP_THREADS)
void mlp_kernel(const float* __restrict__ X,
                const float* __restrict__ W1, const float* __restrict__ b1,
                const float* __restrict__ W2, const float* __restrict__ b2,
                float* __restrict__ out) {
    __shared__ float sW1[3 * DD * HH];   // [12][100] row-major
    __shared__ float sb1[HH];
    __shared__ float sW2[HH];

    for (int i = threadIdx.x; i < 3 * DD * HH; i += MLP_THREADS) sW1[i] = W1[i];
    for (int i = threadIdx.x; i < HH; i += MLP_THREADS) {
        sb1[i] = b1[i];
        sW2[i] = W2[i];
    }
    __syncthreads();

    int t = blockIdx.x * MLP_THREADS + threadIdx.x;
    int n = t / TPN;          // node
    int q = t % TPN;          // quarter of hidden units
    if (n >= NN) return;

    float in[3 * DD];
    float4 a = reinterpret_cast<const float4*>(g_mi)[n];
    float4 b = reinterpret_cast<const float4*>(g_mo)[n];
    float4 c = reinterpret_cast<const float4*>(X)[n];
    in[0] = a.x; in[1] = a.y; in[2]  = a.z; in[3]  = a.w;
    in[4] = b.x; in[5] = b.y; in[6]  = b.z; in[7]  = b.w;
    in[8] = c.x; in[9] = c.y; in[10] = c.z; in[11] = c.w;

    float acc = 0.0f;
    const int j0 = q * HPT;
    #pragma unroll 5
    for (int jj = 0; jj < HPT; ++jj) {
        const int j = j0 + jj;
        float s = sb1[j];
        #pragma unroll
        for (int i = 0; i < 3 * DD; ++i)
            s = fmaf(in[i], sW1[i * HH + j], s);
        acc = fmaf(fast_tanh(s), sW2[j], acc);
    }

    // reduce the 4 partial sums within the node's thread quad
    acc += __shfl_xor_sync(0xFFFFFFFFu, acc, 1);
    acc += __shfl_xor_sync(0xFFFFFFFFu, acc, 2);

    if (q == 0) {
        acc += b2[0];
        out[n] = 1.0f / (1.0f + __expf(-acc));
    }
}

// ---------------------------------------------------------------------------
// Launch
// Inputs (metadata order): X, e, Ri, Ro, W1, b1, W2, b2
// ---------------------------------------------------------------------------
extern "C" void kernel_launch(void* const* d_in, const int* in_sizes, int n_in,
                              void* d_out, int out_size) {
    const float* X  = (const float*)d_in[0];
    const float* e  = (const float*)d_in[1];
    const float* Ri = (const float*)d_in[2];
    const float* Ro = (const float*)d_in[3];
    const float* W1 = (const float*)d_in[4];
    const float* b1 = (const float*)d_in[5];
    const float* W2 = (const float*)d_in[6];
    const float* b2 = (const float*)d_in[7];
    float* out = (float*)d_out;

    // 1) scan Ri/Ro (HBM-bound) with inline rendezvous scatter + zeroing
    dim3 grid(EE / COLS_PER_BLOCK, ROW_CHUNKS, 2);   // (24, 64, 2) = 3072 blocks
    find_scatter_kernel<<<grid, SCAN_THREADS>>>(Ri, Ro, X, e);

    // 2) fused MLP (4 threads/node, 256 blocks)
    mlp_kernel<<<(NN * TPN + MLP_THREADS - 1) / MLP_THREADS, MLP_THREADS>>>(
        X, W1, b1, W2, b2, out);
}

// round 9
// speedup vs baseline: 1.0171x; 1.0088x over previous
#include <cuda_runtime.h>
#include <cuda_bf16.h>
#include <math.h>

// Problem constants (fixed by the dataset)
#define NN 8192      // nodes
#define EE 24576     // edges
#define DD 4         // node feature dim
#define HH 100       // hidden units

// ---------------------------------------------------------------------------
// Device scratch (no allocations allowed in kernel_launch)
// ---------------------------------------------------------------------------
__device__ unsigned int g_tag[EE];     // per-edge rendezvous: 0 = empty, else idx+1
__device__ float g_mi[NN * DD];
__device__ float g_mo[NN * DD];

// ---------------------------------------------------------------------------
// Kernel 1: scan the dense one-hot incidence matrices AND scatter inline.
//
// Each column of Ri/Ro [N, E] (row-major) has exactly one 1.0; over a row
// chunk compute fidx = sum_r r*M[r,c], found = sum_r M[r,c]. The unique chunk
// holding the 1.0 knows the index. Per edge there are exactly TWO finders
// (one in a z=0 block -> idx_i, one in a z=1 block -> idx_o). They rendezvous
// via atomicExch on g_tag[k]: first arriver deposits its index (+1); second
// arriver receives the other index in the exchange return value (the value
// travels through the atomic -> no fence needed) and performs the scatter:
//   mi[idx_i] += e[k] * X[idx_o] ;  mo[idx_o] += e[k] * X[idx_i]
//
// This kernel is the HBM roofline: 2 * N * E * 4B = 1.61 GB streamed once.
// Scan config converged at ~7.25 TB/s (BATCH 8, 4 blocks/SM).
// ---------------------------------------------------------------------------
#define SCAN_THREADS     256
#define COLS_PER_BLOCK   (SCAN_THREADS * 4)      // 1024
#define ROW_CHUNKS       64
#define ROWS_PER_CHUNK   (NN / ROW_CHUNKS)       // 128
#define BATCH            8

__device__ __forceinline__ void rendezvous_scatter(
    int c, float fidx, float found, int z,
    const float* __restrict__ X, const float* __restrict__ e)
{
    if (found == 0.f) return;
    int my = (int)fidx;
    unsigned old = atomicExch(&g_tag[c], (unsigned)(my + 1));
    if (old == 0u) return;            // first arriver: just deposited
    int other = (int)old - 1;
    int ii = (z == 0) ? my    : other;
    int io = (z == 0) ? other : my;

    float ek = e[c];
    float4 xo = reinterpret_cast<const float4*>(X)[io];
    float4 xi = reinterpret_cast<const float4*>(X)[ii];

    float* mi = g_mi + 4 * ii;
    atomicAdd(mi + 0, ek * xo.x);
    atomicAdd(mi + 1, ek * xo.y);
    atomicAdd(mi + 2, ek * xo.z);
    atomicAdd(mi + 3, ek * xo.w);

    float* mo = g_mo + 4 * io;
    atomicAdd(mo + 0, ek * xi.x);
    atomicAdd(mo + 1, ek * xi.y);
    atomicAdd(mo + 2, ek * xi.z);
    atomicAdd(mo + 3, ek * xi.w);
}

__global__ __launch_bounds__(SCAN_THREADS, 4)
void find_scatter_kernel(const float* __restrict__ Ri,
                         const float* __restrict__ Ro,
                         const float* __restrict__ X,
                         const float* __restrict__ e) {
    // --- prologue: zero accumulators + rendezvous tags (wave-1 blocks) ---
    if (blockIdx.z == 0 && blockIdx.y < 8) {
        int t = (blockIdx.y * gridDim.x + blockIdx.x) * SCAN_THREADS + threadIdx.x;
        if (t < NN * DD) { g_mi[t] = 0.0f; g_mo[t] = 0.0f; }
        if (t < EE)      g_tag[t] = 0u;
    }

    const int z = blockIdx.z;
    const float* M = (z == 0) ? Ri : Ro;

    const int col = blockIdx.x * COLS_PER_BLOCK + threadIdx.x * 4;
    const int r0  = blockIdx.y * ROWS_PER_CHUNK;

    const float4* p = reinterpret_cast<const float4*>(M + (long)r0 * EE + col);
    const int row_stride4 = EE / 4;  // float4 elements per row

    float fi0 = 0.f, fi1 = 0.f, fi2 = 0.f, fi3 = 0.f;
    float ff0 = 0.f, ff1 = 0.f, ff2 = 0.f, ff3 = 0.f;

    for (int rb = 0; rb < ROWS_PER_CHUNK; rb += BATCH) {
        // front-batch BATCH independent LDG.128s (deep MLP)
        float4 v[BATCH];
        #pragma unroll
        for (int j = 0; j < BATCH; ++j)
            v[j] = __ldcs(p + (long)(rb + j) * row_stride4);   // streaming

        #pragma unroll
        for (int j = 0; j < BATCH; ++j) {
            float fr = (float)(r0 + rb + j);
            fi0 = fmaf(v[j].x, fr, fi0); ff0 += v[j].x;
            fi1 = fmaf(v[j].y, fr, fi1); ff1 += v[j].y;
            fi2 = fmaf(v[j].z, fr, fi2); ff2 += v[j].z;
            fi3 = fmaf(v[j].w, fr, fi3); ff3 += v[j].w;
        }
    }

    // --- epilogue: rendezvous + inline scatter (second arriver does work) ---
    rendezvous_scatter(col + 0, fi0, ff0, z, X, e);
    rendezvous_scatter(col + 1, fi1, ff1, z, X, e);
    rendezvous_scatter(col + 2, fi2, ff2, z, X, e);
    rendezvous_scatter(col + 3, fi3, ff3, z, X, e);
}

// ---------------------------------------------------------------------------
// Fast device math
// ---------------------------------------------------------------------------
__device__ __forceinline__ float fast_tanh(float x) {
    float y;
    asm("tanh.approx.f32 %0, %1;" : "=f"(y) : "f"(x));
    return y;
}

// ---------------------------------------------------------------------------
// Kernel 2: fused MLP  out = sigmoid( tanh([mi,mo,X] @ W1 + b1) @ W2 + b2 )
// R9: warp-per-node. Lane l computes hidden units {l, l+32, l+64, l+96}
// (4 independent 12-FMA chains, guard j<100), butterfly shfl reduce, lane 0
// writes. 8192 warps -> 1024 blocks x 256 threads: real occupancy, short
// per-lane serial chain.
// ---------------------------------------------------------------------------
#define MLP_THREADS 256
#define NODES_PER_BLOCK (MLP_THREADS / 32)   // 8

__global__ __launch_bounds__(MLP_THREADS)
void mlp_kernel(const float* __restrict__ X,
                const float* __restrict__ W1, const float* __restrict__ b1,
                const float* __restrict__ W2, const float* __restrict__ b2,
                float* __restrict__ out) {
    __shared__ float sW1[3 * DD * HH];   // [12][100] row-major
    __shared__ float sb1[HH];
    __shared__ float sW2[HH];

    for (int i = threadIdx.x; i < 3 * DD * HH; i += MLP_THREADS) sW1[i] = W1[i];
    for (int i = threadIdx.x; i < HH; i += MLP_THREADS) {
        sb1[i] = b1[i];
        sW2[i] = W2[i];
    }
    __syncthreads();

    const int warp = threadIdx.x >> 5;
    const int lane = threadIdx.x & 31;
    const int n    = blockIdx.x * NODES_PER_BLOCK + warp;
    if (n >= NN) return;

    // node input vector (same addresses across warp -> broadcast loads)
    float in[3 * DD];
    float4 a = reinterpret_cast<const float4*>(g_mi)[n];
    float4 b = reinterpret_cast<const float4*>(g_mo)[n];
    float4 c = reinterpret_cast<const float4*>(X)[n];
    in[0] = a.x; in[1] = a.y; in[2]  = a.z; in[3]  = a.w;
    in[4] = b.x; in[5] = b.y; in[6]  = b.z; in[7]  = b.w;
    in[8] = c.x; in[9] = c.y; in[10] = c.z; in[11] = c.w;

    float acc = 0.0f;
    #pragma unroll
    for (int jj = 0; jj < 4; ++jj) {
        const int j = jj * 32 + lane;
        if (j < HH) {
            float s = sb1[j];
            #pragma unroll
            for (int i = 0; i < 3 * DD; ++i)
                s = fmaf(in[i], sW1[i * HH + j], s);
            acc = fmaf(fast_tanh(s), sW2[j], acc);
        }
    }

    // warp butterfly reduce
    acc += __shfl_xor_sync(0xFFFFFFFFu, acc, 16);
    acc += __shfl_xor_sync(0xFFFFFFFFu, acc, 8);
    acc += __shfl_xor_sync(0xFFFFFFFFu, acc, 4);
    acc += __shfl_xor_sync(0xFFFFFFFFu, acc, 2);
    acc += __shfl_xor_sync(0xFFFFFFFFu, acc, 1);

    if (lane == 0) {
        acc += b2[0];
        out[n] = 1.0f / (1.0f + __expf(-acc));
    }
}

// ---------------------------------------------------------------------------
// Launch
// Inputs (metadata order): X, e, Ri, Ro, W1, b1, W2, b2
// ---------------------------------------------------------------------------
extern "C" void kernel_launch(void* const* d_in, const int* in_sizes, int n_in,
                              void* d_out, int out_size) {
    const float* X  = (const float*)d_in[0];
    const float* e  = (const float*)d_in[1];
    const float* Ri = (const float*)d_in[2];
    const float* Ro = (const float*)d_in[3];
    const float* W1 = (const float*)d_in[4];
    const float* b1 = (const float*)d_in[5];
    const float* W2 = (const float*)d_in[6];
    const float* b2 = (const float*)d_in[7];
    float* out = (float*)d_out;

    // 1) scan Ri/Ro (HBM-bound) with inline rendezvous scatter + zeroing
    dim3 grid(EE / COLS_PER_BLOCK, ROW_CHUNKS, 2);   // (24, 64, 2) = 3072 blocks
    find_scatter_kernel<<<grid, SCAN_THREADS>>>(Ri, Ro, X, e);

    // 2) fused MLP, warp-per-node (1024 blocks x 256 threads)
    mlp_kernel<<<NN / NODES_PER_BLOCK, MLP_THREADS>>>(X, W1, b1, W2, b2, out);
}

// round 10
// speedup vs baseline: 1.0269x; 1.0096x over previous
#include <cuda_runtime.h>
#include <cuda_bf16.h>
#include <math.h>

// Problem constants (fixed by the dataset)
#define NN 8192      // nodes
#define EE 24576     // edges
#define DD 4         // node feature dim
#define HH 100       // hidden units

// ---------------------------------------------------------------------------
// Device scratch (no allocations allowed in kernel_launch)
// ---------------------------------------------------------------------------
__device__ unsigned int g_tag[EE];     // per-edge rendezvous: 0 = empty, else idx+1
__device__ float g_mi[NN * DD];
__device__ float g_mo[NN * DD];

// ---------------------------------------------------------------------------
// Kernel 1: scan the dense one-hot incidence matrices AND scatter inline.
//
// Each column of Ri/Ro [N, E] (row-major) has exactly one 1.0; over a row
// chunk compute fidx = sum_r r*M[r,c], found = sum_r M[r,c]. The unique chunk
// holding the 1.0 knows the index. Per edge there are exactly TWO finders
// (one in a z=0 block -> idx_i, one in a z=1 block -> idx_o). They rendezvous
// via atomicExch on g_tag[k]: first arriver deposits its index (+1); second
// arriver receives the other index in the exchange return value (the value
// travels through the atomic -> no fence needed) and performs the scatter:
//   mi[idx_i] += e[k] * X[idx_o] ;  mo[idx_o] += e[k] * X[idx_i]
//
// This kernel is the HBM roofline: 2 * N * E * 4B = 1.61 GB streamed once.
// Scan config converged at ~7.25 TB/s (BATCH 8, 4 blocks/SM).
// ---------------------------------------------------------------------------
#define SCAN_THREADS     256
#define COLS_PER_BLOCK   (SCAN_THREADS * 4)      // 1024
#define ROW_CHUNKS       64
#define ROWS_PER_CHUNK   (NN / ROW_CHUNKS)       // 128
#define BATCH            8

__device__ __forceinline__ void rendezvous_scatter(
    int c, float fidx, float found, int z,
    const float* __restrict__ X, const float* __restrict__ e)
{
    if (found == 0.f) return;
    int my = (int)fidx;
    unsigned old = atomicExch(&g_tag[c], (unsigned)(my + 1));
    if (old == 0u) return;            // first arriver: just deposited
    int other = (int)old - 1;
    int ii = (z == 0) ? my    : other;
    int io = (z == 0) ? other : my;

    float ek = e[c];
    float4 xo = reinterpret_cast<const float4*>(X)[io];
    float4 xi = reinterpret_cast<const float4*>(X)[ii];

    float* mi = g_mi + 4 * ii;
    atomicAdd(mi + 0, ek * xo.x);
    atomicAdd(mi + 1, ek * xo.y);
    atomicAdd(mi + 2, ek * xo.z);
    atomicAdd(mi + 3, ek * xo.w);

    float* mo = g_mo + 4 * io;
    atomicAdd(mo + 0, ek * xi.x);
    atomicAdd(mo + 1, ek * xi.y);
    atomicAdd(mo + 2, ek * xi.z);
    atomicAdd(mo + 3, ek * xi.w);
}

__global__ __launch_bounds__(SCAN_THREADS, 4)
void find_scatter_kernel(const float* __restrict__ Ri,
                         const float* __restrict__ Ro,
                         const float* __restrict__ X,
                         const float* __restrict__ e) {
    // --- prologue: zero accumulators + rendezvous tags (wave-1 blocks) ---
    if (blockIdx.z == 0 && blockIdx.y < 8) {
        int t = (blockIdx.y * gridDim.x + blockIdx.x) * SCAN_THREADS + threadIdx.x;
        if (t < NN * DD) { g_mi[t] = 0.0f; g_mo[t] = 0.0f; }
        if (t < EE)      g_tag[t] = 0u;
    }

    const int z = blockIdx.z;
    const float* M = (z == 0) ? Ri : Ro;

    const int col = blockIdx.x * COLS_PER_BLOCK + threadIdx.x * 4;
    const int r0  = blockIdx.y * ROWS_PER_CHUNK;

    const float4* p = reinterpret_cast<const float4*>(M + (long)r0 * EE + col);
    const int row_stride4 = EE / 4;  // float4 elements per row

    float fi0 = 0.f, fi1 = 0.f, fi2 = 0.f, fi3 = 0.f;
    float ff0 = 0.f, ff1 = 0.f, ff2 = 0.f, ff3 = 0.f;

    for (int rb = 0; rb < ROWS_PER_CHUNK; rb += BATCH) {
        // front-batch BATCH independent LDG.128s (deep MLP)
        float4 v[BATCH];
        #pragma unroll
        for (int j = 0; j < BATCH; ++j)
            v[j] = __ldcs(p + (long)(rb + j) * row_stride4);   // streaming

        #pragma unroll
        for (int j = 0; j < BATCH; ++j) {
            float fr = (float)(r0 + rb + j);
            fi0 = fmaf(v[j].x, fr, fi0); ff0 += v[j].x;
            fi1 = fmaf(v[j].y, fr, fi1); ff1 += v[j].y;
            fi2 = fmaf(v[j].z, fr, fi2); ff2 += v[j].z;
            fi3 = fmaf(v[j].w, fr, fi3); ff3 += v[j].w;
        }
    }

    // --- epilogue: rendezvous + inline scatter (second arriver does work) ---
    rendezvous_scatter(col + 0, fi0, ff0, z, X, e);
    rendezvous_scatter(col + 1, fi1, ff1, z, X, e);
    rendezvous_scatter(col + 2, fi2, ff2, z, X, e);
    rendezvous_scatter(col + 3, fi3, ff3, z, X, e);
}

// ---------------------------------------------------------------------------
// Fast device math
// ---------------------------------------------------------------------------
__device__ __forceinline__ float fast_tanh(float x) {
    float y;
    asm("tanh.approx.f32 %0, %1;" : "=f"(y) : "f"(x));
    return y;
}

// ---------------------------------------------------------------------------
// Kernel 2: fused MLP  out = sigmoid( tanh([mi,mo,X] @ W1 + b1) @ W2 + b2 )
// R10: warp-per-node body kept; preload cost attacked:
//  - 4 nodes per warp (sequential) -> 256 blocks, preload replication / 4
//  - float4-vectorized smem staging  -> preload instructions / 4
// Lane l computes hidden units {l, l+32, l+64, l+96} per node, butterfly
// shfl reduce, lane 0 writes.
// ---------------------------------------------------------------------------
#define MLP_THREADS 256
#define WARPS_PER_BLOCK (MLP_THREADS / 32)               // 8
#define NODES_PER_WARP  4
#define NODES_PER_BLOCK (WARPS_PER_BLOCK * NODES_PER_WARP) // 32
#define W1_F4   (3 * DD * HH / 4)                         // 300 float4
#define TAIL_F4 ((HH + HH + 4 + 3) / 4)                   // b1(100)+W2(100)+b2 pad -> 51

__global__ __launch_bounds__(MLP_THREADS)
void mlp_kernel(const float* __restrict__ X,
                const float* __restrict__ W1, const float* __restrict__ b1,
                const float* __restrict__ W2, const float* __restrict__ b2,
                float* __restrict__ out) {
    __shared__ float4 sW1_4[W1_F4];       // [12][100] row-major, float4 view
    __shared__ float  sb1[HH];
    __shared__ float  sW2[HH + 4];        // +pad so float4 copies are safe

    const float* sW1 = reinterpret_cast<const float*>(sW1_4);

    // --- vectorized weight staging (W1 is 16B-aligned: 1200 floats) ---
    {
        const float4* W1v = reinterpret_cast<const float4*>(W1);
        for (int i = threadIdx.x; i < W1_F4; i += MLP_THREADS)
            sW1_4[i] = W1v[i];
        // b1 / W2 are 100 floats each (not necessarily float4-mult) -> scalar,
        // but only 200 total ops across the block.
        for (int i = threadIdx.x; i < HH; i += MLP_THREADS) {
            sb1[i] = b1[i];
            sW2[i] = W2[i];
        }
    }
    __syncthreads();

    const int warp = threadIdx.x >> 5;
    const int lane = threadIdx.x & 31;
    const int n0   = (blockIdx.x * WARPS_PER_BLOCK + warp) * NODES_PER_WARP;
    const float bias2 = __ldg(b2);

    #pragma unroll
    for (int nn = 0; nn < NODES_PER_WARP; ++nn) {
        const int n = n0 + nn;

        // node input vector (same addresses across warp -> broadcast loads)
        float in[3 * DD];
        float4 a = reinterpret_cast<const float4*>(g_mi)[n];
        float4 b = reinterpret_cast<const float4*>(g_mo)[n];
        float4 c = reinterpret_cast<const float4*>(X)[n];
        in[0] = a.x; in[1] = a.y; in[2]  = a.z; in[3]  = a.w;
        in[4] = b.x; in[5] = b.y; in[6]  = b.z; in[7]  = b.w;
        in[8] = c.x; in[9] = c.y; in[10] = c.z; in[11] = c.w;

        float acc = 0.0f;
        #pragma unroll
        for (int jj = 0; jj < 4; ++jj) {
            const int j = jj * 32 + lane;
            if (j < HH) {
                float s = sb1[j];
                #pragma unroll
                for (int i = 0; i < 3 * DD; ++i)
                    s = fmaf(in[i], sW1[i * HH + j], s);
                acc = fmaf(fast_tanh(s), sW2[j], acc);
            }
        }

        // warp butterfly reduce
        acc += __shfl_xor_sync(0xFFFFFFFFu, acc, 16);
        acc += __shfl_xor_sync(0xFFFFFFFFu, acc, 8);
        acc += __shfl_xor_sync(0xFFFFFFFFu, acc, 4);
        acc += __shfl_xor_sync(0xFFFFFFFFu, acc, 2);
        acc += __shfl_xor_sync(0xFFFFFFFFu, acc, 1);

        if (lane == 0)
            out[n] = 1.0f / (1.0f + __expf(-(acc + bias2)));
    }
}

// ---------------------------------------------------------------------------
// Launch
// Inputs (metadata order): X, e, Ri, Ro, W1, b1, W2, b2
// ---------------------------------------------------------------------------
extern "C" void kernel_launch(void* const* d_in, const int* in_sizes, int n_in,
                              void* d_out, int out_size) {
    const float* X  = (const float*)d_in[0];
    const float* e  = (const float*)d_in[1];
    const float* Ri = (const float*)d_in[2];
    const float* Ro = (const float*)d_in[3];
    const float* W1 = (const float*)d_in[4];
    const float* b1 = (const float*)d_in[5];
    const float* W2 = (const float*)d_in[6];
    const float* b2 = (const float*)d_in[7];
    float* out = (float*)d_out;

    // 1) scan Ri/Ro (HBM-bound) with inline rendezvous scatter + zeroing
    dim3 grid(EE / COLS_PER_BLOCK, ROW_CHUNKS, 2);   // (24, 64, 2) = 3072 blocks
    find_scatter_kernel<<<grid, SCAN_THREADS>>>(Ri, Ro, X, e);

    // 2) fused MLP: 4 nodes/warp, vectorized weight staging (256 blocks)
    mlp_kernel<<<NN / NODES_PER_BLOCK, MLP_THREADS>>>(X, W1, b1, W2, b2, out);
}

// round 11
// speedup vs baseline: 1.0287x; 1.0017x over previous
#include <cuda_runtime.h>
#include <cuda_bf16.h>
#include <math.h>

// Problem constants (fixed by the dataset)
#define NN 8192      // nodes
#define EE 24576     // edges
#define DD 4         // node feature dim
#define HH 100       // hidden units

// ---------------------------------------------------------------------------
// Device scratch (no allocations allowed in kernel_launch)
// ---------------------------------------------------------------------------
__device__ unsigned int g_tag[EE];     // per-edge rendezvous: 0 = empty, else idx+1
__device__ float g_mi[NN * DD];
__device__ float g_mo[NN * DD];

// ---------------------------------------------------------------------------
// Kernel 1: scan the dense one-hot incidence matrices AND scatter inline.
//
// Each column of Ri/Ro [N, E] (row-major) has exactly one 1.0; over a row
// chunk compute fidx = sum_r r*M[r,c], found = sum_r M[r,c]. The unique chunk
// holding the 1.0 knows the index. Per edge there are exactly TWO finders
// (one in a z=0 block -> idx_i, one in a z=1 block -> idx_o). They rendezvous
// via atomicExch on g_tag[k]: first arriver deposits its index (+1); second
// arriver receives the other index in the exchange return value (the value
// travels through the atomic -> no fence needed) and performs the scatter:
//   mi[idx_i] += e[k] * X[idx_o] ;  mo[idx_o] += e[k] * X[idx_i]
//
// This kernel is the HBM roofline: 2 * N * E * 4B = 1.61 GB streamed once.
// Scan config converged at ~7.25 TB/s (BATCH 8, 4 blocks/SM).
// ---------------------------------------------------------------------------
#define SCAN_THREADS     256
#define COLS_PER_BLOCK   (SCAN_THREADS * 4)      // 1024
#define ROW_CHUNKS       64
#define ROWS_PER_CHUNK   (NN / ROW_CHUNKS)       // 128
#define BATCH            8

__device__ __forceinline__ void rendezvous_scatter(
    int c, float fidx, float found, int z,
    const float* __restrict__ X, const float* __restrict__ e)
{
    if (found == 0.f) return;
    int my = (int)fidx;
    unsigned old = atomicExch(&g_tag[c], (unsigned)(my + 1));
    if (old == 0u) return;            // first arriver: just deposited
    int other = (int)old - 1;
    int ii = (z == 0) ? my    : other;
    int io = (z == 0) ? other : my;

    float ek = e[c];
    float4 xo = reinterpret_cast<const float4*>(X)[io];
    float4 xi = reinterpret_cast<const float4*>(X)[ii];

    float* mi = g_mi + 4 * ii;
    atomicAdd(mi + 0, ek * xo.x);
    atomicAdd(mi + 1, ek * xo.y);
    atomicAdd(mi + 2, ek * xo.z);
    atomicAdd(mi + 3, ek * xo.w);

    float* mo = g_mo + 4 * io;
    atomicAdd(mo + 0, ek * xi.x);
    atomicAdd(mo + 1, ek * xi.y);
    atomicAdd(mo + 2, ek * xi.z);
    atomicAdd(mo + 3, ek * xi.w);
}

__global__ __launch_bounds__(SCAN_THREADS, 4)
void find_scatter_kernel(const float* __restrict__ Ri,
                         const float* __restrict__ Ro,
                         const float* __restrict__ X,
                         const float* __restrict__ e) {
    // --- prologue: zero accumulators + rendezvous tags (wave-1 blocks) ---
    if (blockIdx.z == 0 && blockIdx.y < 8) {
        int t = (blockIdx.y * gridDim.x + blockIdx.x) * SCAN_THREADS + threadIdx.x;
        if (t < NN * DD) { g_mi[t] = 0.0f; g_mo[t] = 0.0f; }
        if (t < EE)      g_tag[t] = 0u;
    }

    const int z = blockIdx.z;
    const float* M = (z == 0) ? Ri : Ro;

    const int col = blockIdx.x * COLS_PER_BLOCK + threadIdx.x * 4;
    const int r0  = blockIdx.y * ROWS_PER_CHUNK;

    const float4* p = reinterpret_cast<const float4*>(M + (long)r0 * EE + col);
    const int row_stride4 = EE / 4;  // float4 elements per row

    float fi0 = 0.f, fi1 = 0.f, fi2 = 0.f, fi3 = 0.f;
    float ff0 = 0.f, ff1 = 0.f, ff2 = 0.f, ff3 = 0.f;

    for (int rb = 0; rb < ROWS_PER_CHUNK; rb += BATCH) {
        // front-batch BATCH independent LDG.128s (deep MLP)
        float4 v[BATCH];
        #pragma unroll
        for (int j = 0; j < BATCH; ++j)
            v[j] = __ldcs(p + (long)(rb + j) * row_stride4);   // streaming

        #pragma unroll
        for (int j = 0; j < BATCH; ++j) {
            float fr = (float)(r0 + rb + j);
            fi0 = fmaf(v[j].x, fr, fi0); ff0 += v[j].x;
            fi1 = fmaf(v[j].y, fr, fi1); ff1 += v[j].y;
            fi2 = fmaf(v[j].z, fr, fi2); ff2 += v[j].z;
            fi3 = fmaf(v[j].w, fr, fi3); ff3 += v[j].w;
        }
    }

    // --- epilogue: rendezvous + inline scatter (second arriver does work) ---
    rendezvous_scatter(col + 0, fi0, ff0, z, X, e);
    rendezvous_scatter(col + 1, fi1, ff1, z, X, e);
    rendezvous_scatter(col + 2, fi2, ff2, z, X, e);
    rendezvous_scatter(col + 3, fi3, ff3, z, X, e);
}

// ---------------------------------------------------------------------------
// Fast device math
// ---------------------------------------------------------------------------
__device__ __forceinline__ float fast_tanh(float x) {
    float y;
    asm("tanh.approx.f32 %0, %1;" : "=f"(y) : "f"(x));
    return y;
}

// ---------------------------------------------------------------------------
// Kernel 2: fused MLP  out = sigmoid( tanh([mi,mo,X] @ W1 + b1) @ W2 + b2 )
// R11: NO shared memory, NO __syncthreads. Weights are node-invariant, so
// each lane holds its 4 W1 columns in REGISTERS (w1r[4][12] + b1r + w2r),
// loaded once per warp via coalesced gmem reads (lane-consecutive, L1/L2-hit
// after block 0). Lanes with j >= 100 get zero weights -> contribute
// tanh(0)*0 = 0, no guard in the hot loop. 4 independent j-chains x 4
// independent nodes per warp give the scheduler ILP to hide latency.
// ---------------------------------------------------------------------------
#define MLP_THREADS 256
#define WARPS_PER_BLOCK (MLP_THREADS / 32)                  // 8
#define NODES_PER_WARP  4
#define NODES_PER_BLOCK (WARPS_PER_BLOCK * NODES_PER_WARP)  // 32

__global__ __launch_bounds__(MLP_THREADS)
void mlp_kernel(const float* __restrict__ X,
                const float* __restrict__ W1, const float* __restrict__ b1,
                const float* __restrict__ W2, const float* __restrict__ b2,
                float* __restrict__ out) {
    const int warp = threadIdx.x >> 5;
    const int lane = threadIdx.x & 31;
    const int n0   = (blockIdx.x * WARPS_PER_BLOCK + warp) * NODES_PER_WARP;

    // --- load this lane's weight columns into registers (coalesced) ---
    float w1r[4][3 * DD];
    float b1r[4], w2r[4];
    #pragma unroll
    for (int jj = 0; jj < 4; ++jj) {
        const int j = jj * 32 + lane;
        const bool ok = (j < HH);
        b1r[jj] = ok ? __ldg(b1 + j) : 0.0f;
        w2r[jj] = ok ? __ldg(W2 + j) : 0.0f;
        #pragma unroll
        for (int i = 0; i < 3 * DD; ++i)
            w1r[jj][i] = ok ? __ldg(W1 + i * HH + j) : 0.0f;
    }
    const float bias2 = __ldg(b2);

    #pragma unroll
    for (int nn = 0; nn < NODES_PER_WARP; ++nn) {
        const int n = n0 + nn;

        // node input vector (same addresses across warp -> broadcast loads)
        float in[3 * DD];
        float4 a = reinterpret_cast<const float4*>(g_mi)[n];
        float4 b = reinterpret_cast<const float4*>(g_mo)[n];
        float4 c = reinterpret_cast<const float4*>(X)[n];
        in[0] = a.x; in[1] = a.y; in[2]  = a.z; in[3]  = a.w;
        in[4] = b.x; in[5] = b.y; in[6]  = b.z; in[7]  = b.w;
        in[8] = c.x; in[9] = c.y; in[10] = c.z; in[11] = c.w;

        float acc = 0.0f;
        #pragma unroll
        for (int jj = 0; jj < 4; ++jj) {
            float s = b1r[jj];
            #pragma unroll
            for (int i = 0; i < 3 * DD; ++i)
                s = fmaf(in[i], w1r[jj][i], s);
            acc = fmaf(fast_tanh(s), w2r[jj], acc);   // zero-weight lanes add 0
        }

        // warp butterfly reduce
        acc += __shfl_xor_sync(0xFFFFFFFFu, acc, 16);
        acc += __shfl_xor_sync(0xFFFFFFFFu, acc, 8);
        acc += __shfl_xor_sync(0xFFFFFFFFu, acc, 4);
        acc += __shfl_xor_sync(0xFFFFFFFFu, acc, 2);
        acc += __shfl_xor_sync(0xFFFFFFFFu, acc, 1);

        if (lane == 0)
            out[n] = 1.0f / (1.0f + __expf(-(acc + bias2)));
    }
}

// ---------------------------------------------------------------------------
// Launch
// Inputs (metadata order): X, e, Ri, Ro, W1, b1, W2, b2
// ---------------------------------------------------------------------------
extern "C" void kernel_launch(void* const* d_in, const int* in_sizes, int n_in,
                              void* d_out, int out_size) {
    const float* X  = (const float*)d_in[0];
    const float* e  = (const float*)d_in[1];
    const float* Ri = (const float*)d_in[2];
    const float* Ro = (const float*)d_in[3];
    const float* W1 = (const float*)d_in[4];
    const float* b1 = (const float*)d_in[5];
    const float* W2 = (const float*)d_in[6];
    const float* b2 = (const float*)d_in[7];
    float* out = (float*)d_out;

    // 1) scan Ri/Ro (HBM-bound) with inline rendezvous scatter + zeroing
    dim3 grid(EE / COLS_PER_BLOCK, ROW_CHUNKS, 2);   // (24, 64, 2) = 3072 blocks
    find_scatter_kernel<<<grid, SCAN_THREADS>>>(Ri, Ro, X, e);

    // 2) fused MLP: register-resident weights, no smem, no sync (256 blocks)
    mlp_kernel<<<NN / NODES_PER_BLOCK, MLP_THREADS>>>(X, W1, b1, W2, b2, out);
}